// round 7
// baseline (speedup 1.0000x reference)
#include <cuda_runtime.h>
#include <cuda_bf16.h>
#include <cstdint>

// PearsonLoss: x1 [8,32,256,256] f32, x2 same, margin [8,256,256] i32 -> scalar f32
//
// R7: bulk-async pipelined persistent kernel.
// R1-R6 post-mortem: direct-LDG versions plateau at 63% DRAM regardless of
// occupancy (27->55 warps/SM), MLP batching, or block shape -> cross-CTA
// L1tex-queue spread on front-batched LDG bursts. Fix: stop issuing per-thread
// LDGs entirely. 148 persistent blocks (1/SM), 3-stage smem pipeline filled by
// cp.async.bulk (UBLKCP) + mbarrier expect_tx; compute reads smem only.
//
// Tile = 256 pixels x 32 ch x 2 tensors = 64KB/stage. 2048 tiles, dynamic
// assignment via global atomic counter (self-balancing, no 14-vs-13 tail).
// Streaming math: e=exp(x); 5 running sums; EX=EY=1/C exactly;
// score = (S12/(S1 S2 C) - 1/C^2)/sqrt((S11/(S1^2 C)-1/C^2)(S22/(S2^2 C)-1/C^2));
// per_pixel = margin==0 ? 1-score : max(score,0); out = mean.

#define C_CH    32
#define HW      65536
#define NPIX    524288
#define TILE_PX 256
#define NTILES  (NPIX / TILE_PX)                 // 2048
#define STAGES  3
#define TEN_BYTES   (C_CH * TILE_PX * 4)         // 32768 per tensor per stage
#define STAGE_BYTES (2 * TEN_BYTES)              // 65536
#define SMEM_DATA   (STAGES * STAGE_BYTES)       // 196608
#define SMEM_TOTAL  (SMEM_DATA + 128)            // + barriers/ring
#define NBLOCKS     148
#define BLOCK_SIZE  256

__device__ float        g_acc  = 0.0f;
__device__ unsigned int g_tile = 0u;
__device__ unsigned int g_done = 0u;

__device__ __forceinline__ uint32_t smem_u32(const void* p) {
    return (uint32_t)__cvta_generic_to_shared(p);
}
__device__ __forceinline__ void mbar_init(uint32_t a, uint32_t cnt) {
    asm volatile("mbarrier.init.shared.b64 [%0], %1;" :: "r"(a), "r"(cnt) : "memory");
}
__device__ __forceinline__ void mbar_expect_tx(uint32_t a, uint32_t bytes) {
    asm volatile("mbarrier.arrive.expect_tx.shared.b64 _, [%0], %1;"
                 :: "r"(a), "r"(bytes) : "memory");
}
__device__ __forceinline__ void bulk_g2s(uint32_t dst, const void* src,
                                         uint32_t bytes, uint32_t mbar) {
    asm volatile("cp.async.bulk.shared::cta.global.mbarrier::complete_tx::bytes "
                 "[%0], [%1], %2, [%3];"
                 :: "r"(dst), "l"(src), "r"(bytes), "r"(mbar) : "memory");
}
__device__ __forceinline__ void mbar_wait(uint32_t a, uint32_t ph) {
    asm volatile(
        "{\n\t"
        ".reg .pred P;\n\t"
        "WAIT_%=: \n\t"
        "mbarrier.try_wait.parity.acquire.cta.shared::cta.b64 P, [%0], %1, 0x989680;\n\t"
        "@P bra DONE_%=;\n\t"
        "bra WAIT_%=;\n\t"
        "DONE_%=: \n\t"
        "}"
        :: "r"(a), "r"(ph) : "memory");
}

__device__ __forceinline__ float finalize_pixel(float s1, float s2,
                                                float s11, float s22, float s12,
                                                int m) {
    const float invC  = 1.0f / 32.0f;
    const float invC2 = invC * invC;
    float r1 = __frcp_rn(s1);
    float r2 = __frcp_rn(s2);
    float vx  = fmaf(s11 * r1 * r1, invC, -invC2);
    float vy  = fmaf(s22 * r2 * r2, invC, -invC2);
    float num = fmaf(s12 * r1 * r2, invC, -invC2);
    float score = num * rsqrtf(vx * vy);
    return (m == 0) ? (1.0f - score) : fmaxf(score, 0.0f);
}

// Issue the 64 per-channel 1KB bulk copies of tile t into stage s.
// Called by threads 0..63: k = tid; tensor = k>>5, channel = k&31.
__device__ __forceinline__ void issue_tile(const float* __restrict__ x1,
                                           const float* __restrict__ x2,
                                           char* smem_raw, uint32_t mbar_a,
                                           int s, int t, int k) {
    const int tensor = k >> 5;
    const int c      = k & 31;
    const int px0    = t * TILE_PX;
    const int b      = px0 >> 16;          // / HW
    const int hw     = px0 & (HW - 1);
    const float* src = (tensor == 0 ? x1 : x2)
                     + ((size_t)(b * C_CH + c) * HW + hw);
    uint32_t dst = smem_u32(smem_raw) +
                   (uint32_t)(s * STAGE_BYTES + tensor * TEN_BYTES + c * TILE_PX * 4);
    bulk_g2s(dst, src, TILE_PX * 4, mbar_a);
}

__global__ void __launch_bounds__(BLOCK_SIZE, 1)
pearson_loss_kernel(const float* __restrict__ x1,
                    const float* __restrict__ x2,
                    const int*   __restrict__ margin,
                    float* __restrict__ out) {
    extern __shared__ __align__(16) char smem_raw[];
    uint64_t* mbar = (uint64_t*)(smem_raw + SMEM_DATA);       // 3 barriers
    int*      ring = (int*)(smem_raw + SMEM_DATA + 32);       // 3 tile ids
    const int tid = threadIdx.x;

    uint32_t mbar_a[STAGES];
#pragma unroll
    for (int s = 0; s < STAGES; s++) mbar_a[s] = smem_u32(&mbar[s]);

    if (tid == 0) {
#pragma unroll
        for (int s = 0; s < STAGES; s++) mbar_init(mbar_a[s], 1);
        asm volatile("fence.proxy.async.shared::cta;" ::: "memory");
        // Prefill: grab first 3 tiles and arm their barriers.
#pragma unroll
        for (int s = 0; s < STAGES; s++) {
            int t = (int)atomicAdd(&g_tile, 1u);
            ring[s] = t;
            if (t < NTILES) mbar_expect_tx(mbar_a[s], STAGE_BYTES);
        }
    }
    __syncthreads();

    // Issue prefill copies (64 issuing threads per stage).
#pragma unroll
    for (int s = 0; s < STAGES; s++) {
        int t = ring[s];
        if (t < NTILES && tid < 64)
            issue_tile(x1, x2, smem_raw, mbar_a[s], s, t, tid);
    }

    float local = 0.0f;
    int lc = 0;
    while (true) {
        const int s  = lc % STAGES;
        const int ph = (lc / STAGES) & 1;
        const int t  = ring[s];
        if (t >= NTILES) break;

        mbar_wait(mbar_a[s], ph);

        // Compute this tile: thread tid owns pixel t*256+tid.
        const float* sx1 = (const float*)(smem_raw + s * STAGE_BYTES);
        const float* sx2 = sx1 + C_CH * TILE_PX;
        float S1 = 0.f, S2 = 0.f, S11 = 0.f, S22 = 0.f, S12 = 0.f;
#pragma unroll 8
        for (int c = 0; c < C_CH; c++) {
            float a = sx1[c * TILE_PX + tid];
            float v = sx2[c * TILE_PX + tid];
            float e1 = __expf(a);
            float e2 = __expf(v);
            S1 += e1; S2 += e2;
            S11 = fmaf(e1, e1, S11);
            S22 = fmaf(e2, e2, S22);
            S12 = fmaf(e1, e2, S12);
        }
        const int px = t * TILE_PX + tid;
        const int m  = __ldg(&margin[px]);
        local += finalize_pixel(S1, S2, S11, S22, S12, m);

        __syncthreads();   // everyone done reading stage s

        if (tid == 0) {
            int nt = (int)atomicAdd(&g_tile, 1u);
            ring[s] = nt;
            if (nt < NTILES) mbar_expect_tx(mbar_a[s], STAGE_BYTES);
        }
        __syncthreads();   // ring[s] + expect_tx visible before issuing

        {
            int nt = ring[s];
            if (nt < NTILES && tid < 64)
                issue_tile(x1, x2, smem_raw, mbar_a[s], s, nt, tid);
        }
        lc++;
    }

    // Block reduce local sums.
#pragma unroll
    for (int off = 16; off > 0; off >>= 1)
        local += __shfl_xor_sync(0xFFFFFFFF, local, off);

    __shared__ float warp_sums[BLOCK_SIZE / 32];
    const int lane = tid & 31;
    const int wid  = tid >> 5;
    if (lane == 0) warp_sums[wid] = local;
    __syncthreads();

    __shared__ bool is_last;
    if (tid == 0) {
        float ssum = warp_sums[0];
#pragma unroll
        for (int w = 1; w < BLOCK_SIZE / 32; w++) ssum += warp_sums[w];
        atomicAdd(&g_acc, ssum);
        __threadfence();
        unsigned prev = atomicAdd(&g_done, 1u);
        is_last = (prev == (unsigned)(NBLOCKS - 1));
    }
    __syncthreads();

    if (is_last && tid == 0) {
        __threadfence();
        float total = *((volatile float*)&g_acc);
        out[0] = total * (1.0f / (float)NPIX);
        // reset for next graph replay
        g_acc  = 0.0f;
        g_tile = 0u;
        g_done = 0u;
    }
}

extern "C" void kernel_launch(void* const* d_in, const int* in_sizes, int n_in,
                              void* d_out, int out_size) {
    const float* x1     = (const float*)d_in[0];
    const float* x2     = (const float*)d_in[1];
    const int*   margin = (const int*)d_in[2];
    float* out = (float*)d_out;

    cudaFuncSetAttribute(pearson_loss_kernel,
                         cudaFuncAttributeMaxDynamicSharedMemorySize, SMEM_TOTAL);
    pearson_loss_kernel<<<NBLOCKS, BLOCK_SIZE, SMEM_TOTAL>>>(x1, x2, margin, out);
}

// round 9
// speedup vs baseline: 1.4270x; 1.4270x over previous
#include <cuda_runtime.h>
#include <cuda_bf16.h>

// PearsonLoss: x1 [8,32,256,256] f32, x2 same, margin [8,256,256] i32 -> scalar f32
//
// Streaming formulation over C=32 channels (no probability storage):
//   e1=exp(x1), e2=exp(x2); S1,S2,S11,S22,S12 running sums.
//   EX=EY=1/C exactly (softmax sums to 1).
//   score = (S12/(S1*S2*C) - 1/C^2) / sqrt((S11/(S1^2 C)-1/C^2)(S22/(S2^2 C)-1/C^2))
//   per_pixel = margin==0 ? 1-score : max(score,0);  out = mean.
//
// R9 = R8 resubmitted verbatim (R8 bench was a broker/container infra failure;
// this source has never been measured). Recombination of measured winners:
//  - R1's exact hot-loop shape: BLOCK=256, 4px/thread, grid 512, __ldg loads.
//    (Best measured: 26.3us kernel, DRAM 65.1%. All departures — 128-thr
//    blocks, explicit MLP batching, channel-split 2x warps, bulk-async
//    pipeline — measured WORSE: 27.3 / 27.4 / 31.0 / 39.3us.)
//  - R2's proven single-launch finalize: last-block-done via __device__
//    globals (saves the ~2us init-launch overhead R1's bench paid; the final
//    block resets the globals so graph replays stay deterministic).

#define C_CH   32
#define HW     65536          // 256*256
#define NBATCH 8
#define NPIX   (NBATCH * HW)  // 524288
#define PIX_PER_THREAD 4
#define NTHREADS_TOTAL (NPIX / PIX_PER_THREAD)  // 131072
#define BLOCK_SIZE 256
#define NBLOCKS (NTHREADS_TOTAL / BLOCK_SIZE)   // 512

__device__ float        g_acc   = 0.0f;
__device__ unsigned int g_count = 0u;

__device__ __forceinline__ float finalize_pixel(float s1, float s2,
                                                float s11, float s22, float s12,
                                                int m) {
    const float invC  = 1.0f / 32.0f;
    const float invC2 = invC * invC;
    float r1 = __frcp_rn(s1);
    float r2 = __frcp_rn(s2);
    float vx  = fmaf(s11 * r1 * r1, invC, -invC2);   // EX2 - EX^2
    float vy  = fmaf(s22 * r2 * r2, invC, -invC2);   // EY2 - EY^2
    float num = fmaf(s12 * r1 * r2, invC, -invC2);   // EXY - EX*EY
    float score = num * rsqrtf(vx * vy);
    return (m == 0) ? (1.0f - score) : fmaxf(score, 0.0f);
}

__global__ void __launch_bounds__(BLOCK_SIZE)
pearson_loss_kernel(const float* __restrict__ x1,
                    const float* __restrict__ x2,
                    const int*   __restrict__ margin,
                    float* __restrict__ out) {
    const int t  = blockIdx.x * BLOCK_SIZE + threadIdx.x;  // 0..131071
    const int p0 = t * PIX_PER_THREAD;                     // base pixel
    const int b  = p0 >> 16;                               // / HW
    const int hw = p0 & (HW - 1);

    const float4* __restrict__ x1p =
        (const float4*)(x1 + (size_t)b * C_CH * HW + hw);
    const float4* __restrict__ x2p =
        (const float4*)(x2 + (size_t)b * C_CH * HW + hw);
    const int cstride4 = HW / 4;   // float4 stride per channel

    float4 S1  = make_float4(0.f, 0.f, 0.f, 0.f);
    float4 S2  = make_float4(0.f, 0.f, 0.f, 0.f);
    float4 S11 = make_float4(0.f, 0.f, 0.f, 0.f);
    float4 S22 = make_float4(0.f, 0.f, 0.f, 0.f);
    float4 S12 = make_float4(0.f, 0.f, 0.f, 0.f);

#pragma unroll 8
    for (int c = 0; c < C_CH; c++) {
        float4 a = __ldg(&x1p[c * cstride4]);
        float4 v = __ldg(&x2p[c * cstride4]);

        float e1, e2;
        e1 = __expf(a.x); e2 = __expf(v.x);
        S1.x += e1; S2.x += e2;
        S11.x = fmaf(e1, e1, S11.x); S22.x = fmaf(e2, e2, S22.x);
        S12.x = fmaf(e1, e2, S12.x);

        e1 = __expf(a.y); e2 = __expf(v.y);
        S1.y += e1; S2.y += e2;
        S11.y = fmaf(e1, e1, S11.y); S22.y = fmaf(e2, e2, S22.y);
        S12.y = fmaf(e1, e2, S12.y);

        e1 = __expf(a.z); e2 = __expf(v.z);
        S1.z += e1; S2.z += e2;
        S11.z = fmaf(e1, e1, S11.z); S22.z = fmaf(e2, e2, S22.z);
        S12.z = fmaf(e1, e2, S12.z);

        e1 = __expf(a.w); e2 = __expf(v.w);
        S1.w += e1; S2.w += e2;
        S11.w = fmaf(e1, e1, S11.w); S22.w = fmaf(e2, e2, S22.w);
        S12.w = fmaf(e1, e2, S12.w);
    }

    const int4 mg = __ldg(&((const int4*)margin)[t]);

    float local = finalize_pixel(S1.x, S2.x, S11.x, S22.x, S12.x, mg.x)
                + finalize_pixel(S1.y, S2.y, S11.y, S22.y, S12.y, mg.y)
                + finalize_pixel(S1.z, S2.z, S11.z, S22.z, S12.z, mg.z)
                + finalize_pixel(S1.w, S2.w, S11.w, S22.w, S12.w, mg.w);

    // warp reduce
#pragma unroll
    for (int off = 16; off > 0; off >>= 1)
        local += __shfl_xor_sync(0xFFFFFFFF, local, off);

    __shared__ float warp_sums[BLOCK_SIZE / 32];
    const int lane = threadIdx.x & 31;
    const int wid  = threadIdx.x >> 5;
    if (lane == 0) warp_sums[wid] = local;
    __syncthreads();

    __shared__ bool is_last;
    if (threadIdx.x == 0) {
        float s = warp_sums[0];
#pragma unroll
        for (int w = 1; w < BLOCK_SIZE / 32; w++) s += warp_sums[w];
        atomicAdd(&g_acc, s);
        __threadfence();
        unsigned prev = atomicAdd(&g_count, 1u);
        is_last = (prev == (unsigned)(NBLOCKS - 1));
    }
    __syncthreads();

    if (is_last && threadIdx.x == 0) {
        __threadfence();  // make all g_acc contributions visible
        float total = *((volatile float*)&g_acc);
        out[0] = total * (1.0f / (float)NPIX);
        // reset for next graph replay (deterministic relaunch)
        g_acc   = 0.0f;
        g_count = 0u;
    }
}

extern "C" void kernel_launch(void* const* d_in, const int* in_sizes, int n_in,
                              void* d_out, int out_size) {
    const float* x1     = (const float*)d_in[0];
    const float* x2     = (const float*)d_in[1];
    const int*   margin = (const int*)d_in[2];
    float* out = (float*)d_out;

    pearson_loss_kernel<<<NBLOCKS, BLOCK_SIZE>>>(x1, x2, margin, out);
}